// round 16
// baseline (speedup 1.0000x reference)
#include <cuda_runtime.h>
#include <cuda_fp16.h>
#include <mma.h>
#include <math.h>
#include <stdint.h>

using namespace nvcuda;

#define DIM   512
#define NHEAD 8
#define HD    64
#define FFN   2048
#define BB    4
#define TT    2048
#define ROWS  (BB*TT)     // 8192
#define CTX   64

// ---------------- scratch (allocation-free) ----------------
__device__ __half g_xn_h  [ROWS * DIM];
__device__ __half g_qkv_h [ROWS * 3 * DIM];
__device__ __half g_attn_h[ROWS * DIM];
__device__ __half g_hbuf_h[ROWS * FFN];
__device__ float  g_x1    [ROWS * DIM];
// fp16 weights
#define WQKV_OFF 0
#define WOUT_OFF (3 * DIM * DIM)
#define W1_OFF   (WOUT_OFF + DIM * DIM)
#define W2_OFF   (W1_OFF + DIM * FFN)
#define WTOT     (W2_OFF + FFN * DIM)
__device__ __half g_w_h[WTOT];

// ================= helpers =================
__device__ __forceinline__ uint32_t smem_u32(const void* p) {
    uint32_t a;
    asm("{ .reg .u64 t; cvta.to.shared.u64 t, %1; cvt.u32.u64 %0, t; }" : "=r"(a) : "l"(p));
    return a;
}
__device__ __forceinline__ void cp_async16(uint32_t saddr, const void* gaddr) {
    asm volatile("cp.async.cg.shared.global [%0], [%1], 16;" :: "r"(saddr), "l"(gaddr));
}
#define CP_COMMIT() asm volatile("cp.async.commit_group;" ::: "memory")
#define CP_WAIT(n)  asm volatile("cp.async.wait_group %0;" :: "n"(n) : "memory")

// ---- single fused fp32->fp16 weight convert ----
#define F4_QKV (3 * DIM * DIM / 4)
#define F4_OUT (DIM * DIM / 4)
#define F4_W1  (DIM * FFN / 4)
#define F4_W2  (FFN * DIM / 4)
#define F4_TOT (F4_QKV + F4_OUT + F4_W1 + F4_W2)

__global__ void __launch_bounds__(256) f2h_all_kernel(
    const float* __restrict__ w_qkv, const float* __restrict__ w_out,
    const float* __restrict__ w1, const float* __restrict__ w2,
    __half* __restrict__ out)
{
    int i = blockIdx.x * 256 + threadIdx.x;
    if (i >= F4_TOT) return;
    const float* src;
    int rel;
    size_t dsth;
    if (i < F4_QKV) {
        src = w_qkv; rel = i; dsth = WQKV_OFF;
    } else if (i < F4_QKV + F4_OUT) {
        src = w_out; rel = i - F4_QKV; dsth = WOUT_OFF;
    } else if (i < F4_QKV + F4_OUT + F4_W1) {
        src = w1; rel = i - F4_QKV - F4_OUT; dsth = W1_OFF;
    } else {
        src = w2; rel = i - F4_QKV - F4_OUT - F4_W1; dsth = W2_OFF;
    }
    float4 v = ((const float4*)src)[rel];
    __half2 h0 = __floats2half2_rn(v.x, v.y);
    __half2 h1 = __floats2half2_rn(v.z, v.w);
    __half2* p = (__half2*)(out + dsth) + rel * 2;
    p[0] = h0; p[1] = h1;
}

// ================= RMSNorm (half output) =================
__global__ void __launch_bounds__(256) rmsnorm_kernel(
    const float* __restrict__ x, const float* __restrict__ w, __half* __restrict__ y)
{
    int row = blockIdx.x;
    int t = threadIdx.x;
    const float* xr = x + (size_t)row * DIM;
    float v0 = xr[t], v1 = xr[t + 256];
    float s = v0 * v0 + v1 * v1;
    #pragma unroll
    for (int o = 16; o; o >>= 1) s += __shfl_xor_sync(0xffffffffu, s, o);
    __shared__ float red[8];
    if ((t & 31) == 0) red[t >> 5] = s;
    __syncthreads();
    if (t < 8) {
        float r = red[t];
        #pragma unroll
        for (int o = 4; o; o >>= 1) r += __shfl_xor_sync(0xffu, r, o);
        if (t == 0) red[0] = r;
    }
    __syncthreads();
    float inv = 1.0f / sqrtf(red[0] * (1.0f / DIM) + 1e-6f);
    __half* yr = y + (size_t)row * DIM;
    yr[t]       = __float2half_rn(v0 * inv * w[t]);
    yr[t + 256] = __float2half_rn(v1 * inv * w[t + 256]);
}

// ================= wmma fp16 GEMM: 128x128 CTA, 8 warps (64x32 tiles), 2-stage, occ 2 =================
#define KC     64
#define LDA    72
#define LDB    144
#define A_STG_H (128 * LDA)
#define B_STG_H (KC * LDB)
#define STG_H   (A_STG_H + B_STG_H)
#define LDST    136
#define GEMM_SMEM (2 * STG_H * 2)    // 73728 B

template<int EPI>
__global__ void __launch_bounds__(256, 2) gemm_h_kernel(
    const __half* __restrict__ A, const __half* __restrict__ Bg,
    const float* __restrict__ bias, const float* __restrict__ res,
    void* __restrict__ Cv, int N, int K)
{
    extern __shared__ char smraw[];
    __half* smh = (__half*)smraw;
    uint32_t sm_base = smem_u32(smraw);

    int tid = threadIdx.x;
    int wid = tid >> 5;
    int m0 = blockIdx.y * 128;
    int n0 = blockIdx.x * 128;
    int wm = wid >> 2;      // 0..1 -> 64 rows
    int wn = wid & 3;       // 0..3 -> 32 cols

    const int nc = K / KC;

    auto issue_chunk = [&](int ic) {
        uint32_t as_addr = sm_base + (uint32_t)((ic & 1) * STG_H) * 2;
        uint32_t bs_addr = as_addr + A_STG_H * 2;
        #pragma unroll
        for (int i = 0; i < 4; i++) {
            int task = tid + i * 256;
            int r = task >> 3, sg = task & 7;
            cp_async16(as_addr + (uint32_t)(r * LDA + sg * 8) * 2,
                       A + (size_t)(m0 + r) * K + ic * KC + sg * 8);
        }
        #pragma unroll
        for (int i = 0; i < 4; i++) {
            int task = tid + i * 256;
            int r = task >> 4, sg = task & 15;
            cp_async16(bs_addr + (uint32_t)(r * LDB + sg * 8) * 2,
                       Bg + (size_t)(ic * KC + r) * N + n0 + sg * 8);
        }
    };

    wmma::fragment<wmma::accumulator, 16, 16, 16, float> acc[4][2];
    #pragma unroll
    for (int i = 0; i < 4; i++)
        #pragma unroll
        for (int j = 0; j < 2; j++)
            wmma::fill_fragment(acc[i][j], 0.0f);

    issue_chunk(0); CP_COMMIT();

    for (int ic = 0; ic < nc; ic++) {
        if (ic + 1 < nc) { issue_chunk(ic + 1); CP_COMMIT(); CP_WAIT(1); }
        else             { CP_WAIT(0); }
        __syncthreads();

        __half* As = smh + (ic & 1) * STG_H;
        __half* Bs = As + A_STG_H;
        #pragma unroll
        for (int ks = 0; ks < 4; ks++) {
            wmma::fragment<wmma::matrix_a, 16, 16, 16, __half, wmma::row_major> af[4];
            wmma::fragment<wmma::matrix_b, 16, 16, 16, __half, wmma::row_major> bf[2];
            #pragma unroll
            for (int i = 0; i < 4; i++)
                wmma::load_matrix_sync(af[i], As + (size_t)(wm * 64 + i * 16) * LDA + ks * 16, LDA);
            #pragma unroll
            for (int j = 0; j < 2; j++)
                wmma::load_matrix_sync(bf[j], Bs + (size_t)(ks * 16) * LDB + wn * 32 + j * 16, LDB);
            #pragma unroll
            for (int i = 0; i < 4; i++)
                #pragma unroll
                for (int j = 0; j < 2; j++)
                    wmma::mma_sync(acc[i][j], af[i], bf[j], acc[i][j]);
        }
        __syncthreads();
    }

    // ---- epilogue: acc -> fp32 smem stage -> coalesced fused STG ----
    float* stage = (float*)smraw;   // 128 x LDST floats = 69632 B <= 73728
    #pragma unroll
    for (int i = 0; i < 4; i++)
        #pragma unroll
        for (int j = 0; j < 2; j++)
            wmma::store_matrix_sync(stage + (size_t)(wm * 64 + i * 16) * LDST + wn * 32 + j * 16,
                                    acc[i][j], LDST, wmma::mem_row_major);
    __syncthreads();

    #pragma unroll
    for (int jj = 0; jj < 16; jj++) {
        int idx = jj * 256 + tid;
        int m = idx >> 5, g = idx & 31;
        float4 v = *(float4*)(stage + (size_t)m * LDST + g * 4);
        int c = n0 + g * 4;
        if (EPI == 2) {
            float4 b = *(const float4*)(bias + c);
            float4 rr = *(const float4*)(res + (size_t)(m0 + m) * N + c);
            v.x += b.x + rr.x; v.y += b.y + rr.y;
            v.z += b.z + rr.z; v.w += b.w + rr.w;
            *(float4*)((float*)Cv + (size_t)(m0 + m) * N + c) = v;
        } else {
            if (EPI == 1) {
                float4 b = *(const float4*)(bias + c);
                v.x += b.x; v.y += b.y; v.z += b.z; v.w += b.w;
                v.x = 0.5f * v.x * (1.0f + erff(v.x * 0.70710678118654752f));
                v.y = 0.5f * v.y * (1.0f + erff(v.y * 0.70710678118654752f));
                v.z = 0.5f * v.z * (1.0f + erff(v.z * 0.70710678118654752f));
                v.w = 0.5f * v.w * (1.0f + erff(v.w * 0.70710678118654752f));
            }
            __half2 h0 = __floats2half2_rn(v.x, v.y);
            __half2 h1 = __floats2half2_rn(v.z, v.w);
            __half2* p = (__half2*)((__half*)Cv + (size_t)(m0 + m) * N + c);
            p[0] = h0; p[1] = h1;
        }
    }
}

// ================= Banded attention (r12/r15 verbatim): tensor-core, occ 2, block-skipping =================
#define AQ_LD 72    // halves
#define AS_LD 196   // floats
#define AP_LD 200   // halves
#define AO_LD 72    // floats
#define AT_Q   0
#define AT_K   (AT_Q + 64 * AQ_LD * 2)
#define AT_V   0                                      // overlays Q+K after softmax
#define AT_S   (AT_K + 192 * AQ_LD * 2)
#define AT_P   (AT_S + 64 * AS_LD * 4)
#define AT_I   (AT_P + 64 * AP_LD * 2)
#define ATTN_SMEM (AT_I + 64 * 4)                    // 112896 B

__global__ void __launch_bounds__(256, 2) attn_kernel(
    const __half* __restrict__ qkv, __half* __restrict__ out)
{
    extern __shared__ char smraw[];
    __half* Qh = (__half*)(smraw + AT_Q);
    __half* Kh = (__half*)(smraw + AT_K);
    __half* Vh = (__half*)(smraw + AT_V);
    float*  Sf = (float*) (smraw + AT_S);
    __half* Ph = (__half*)(smraw + AT_P);
    float*  Inv = (float*)(smraw + AT_I);

    int tid = threadIdx.x;
    int wid = tid >> 5;
    int qt = blockIdx.x, h = blockIdx.y, b = blockIdx.z;
    int q0 = qt * 64;
    int kbase = q0 - CTX;

    // ---- load Q and K; zero-prefill P ----
    for (int idx = tid; idx < 64 * 8; idx += 256) {
        int r = idx >> 3, d8 = idx & 7;
        uint4 v = *(const uint4*)(qkv + ((size_t)(b * TT + q0 + r)) * (3 * DIM) + h * HD + d8 * 8);
        *(uint4*)(Qh + r * AQ_LD + d8 * 8) = v;
    }
    for (int idx = tid; idx < 192 * 8; idx += 256) {
        int r = idx >> 3, d8 = idx & 7;
        int kg = kbase + r;
        uint4 kvv = {0, 0, 0, 0};
        if (kg >= 0 && kg < TT)
            kvv = *(const uint4*)(qkv + ((size_t)(b * TT + kg)) * (3 * DIM) + h * HD + DIM + d8 * 8);
        *(uint4*)(Kh + r * AQ_LD + d8 * 8) = kvv;
    }
    {   // zero P: 64 rows x 200 halves = 1600 uint4
        uint4 z = {0, 0, 0, 0};
        for (int idx = tid; idx < 1600; idx += 256) {
            int r = idx / 25, d8 = idx % 25;
            *(uint4*)(Ph + r * AP_LD + d8 * 8) = z;
        }
    }
    __syncthreads();

    // ---- S = Q @ K^T (banded: only col-blocks [rb, rb+8] can be valid) ----
    {
        int rb = wid & 3;
        int cb0 = (wid >> 2) * 6;
        wmma::fragment<wmma::accumulator, 16, 16, 16, float> sacc[6];
        #pragma unroll
        for (int j = 0; j < 6; j++) wmma::fill_fragment(sacc[j], 0.0f);
        #pragma unroll
        for (int ks = 0; ks < 4; ks++) {
            wmma::fragment<wmma::matrix_a, 16, 16, 16, __half, wmma::row_major> aq;
            wmma::load_matrix_sync(aq, Qh + (size_t)(rb * 16) * AQ_LD + ks * 16, AQ_LD);
            #pragma unroll
            for (int j = 0; j < 6; j++) {
                int cb = cb0 + j;
                if (cb >= rb && cb <= rb + 8) {
                    wmma::fragment<wmma::matrix_b, 16, 16, 16, __half, wmma::col_major> bk;
                    wmma::load_matrix_sync(bk, Kh + (size_t)(cb * 16) * AQ_LD + ks * 16, AQ_LD);
                    wmma::mma_sync(sacc[j], aq, bk, sacc[j]);
                }
            }
        }
        #pragma unroll
        for (int j = 0; j < 6; j++) {
            int cb = cb0 + j;
            if (cb >= rb && cb <= rb + 8)
                wmma::store_matrix_sync(Sf + (size_t)(rb * 16) * AS_LD + cb * 16,
                                        sacc[j], AS_LD, wmma::mem_row_major);
        }
    }
    __syncthreads();

    // ---- softmax over valid range [lo, hi]; P elsewhere already 0 ----
    {
        const float scale = 0.125f;
        int q = tid >> 2, l = tid & 3;
        int lo = q, t0 = -kbase;
        if (t0 > lo) lo = t0;
        int hi = q + 2 * CTX;
        int t1 = TT - 1 - kbase;
        if (t1 < hi) hi = t1;
        float mx = -1e30f;
        for (int kk = lo + l; kk <= hi; kk += 4)
            mx = fmaxf(mx, Sf[q * AS_LD + kk]);
        mx = fmaxf(mx, __shfl_xor_sync(0xffffffffu, mx, 1));
        mx = fmaxf(mx, __shfl_xor_sync(0xffffffffu, mx, 2));
        mx *= scale;
        float sum = 0.f;
        for (int kk = lo + l; kk <= hi; kk += 4) {
            float e = __expf(Sf[q * AS_LD + kk] * scale - mx);
            Ph[q * AP_LD + kk] = __float2half_rn(e);
            sum += e;
        }
        sum += __shfl_xor_sync(0xffffffffu, sum, 1);
        sum += __shfl_xor_sync(0xffffffffu, sum, 2);
        if (l == 0) Inv[q] = 1.0f / sum;
    }
    __syncthreads();

    // ---- load V into dead Q+K region ----
    for (int idx = tid; idx < 192 * 8; idx += 256) {
        int r = idx >> 3, d8 = idx & 7;
        int kg = kbase + r;
        uint4 vvv = {0, 0, 0, 0};
        if (kg >= 0 && kg < TT)
            vvv = *(const uint4*)(qkv + ((size_t)(b * TT + kg)) * (3 * DIM) + h * HD + 2 * DIM + d8 * 8);
        *(uint4*)(Vh + r * AQ_LD + d8 * 8) = vvv;
    }
    __syncthreads();

    // ---- O = P @ V (banded: k-steps rb..rb+8 only; P zero outside) ----
    {
        int rb = wid & 3;
        int cb0 = (wid >> 2) * 2;
        wmma::fragment<wmma::accumulator, 16, 16, 16, float> oacc[2];
        #pragma unroll
        for (int j = 0; j < 2; j++) wmma::fill_fragment(oacc[j], 0.0f);
        #pragma unroll
        for (int s = 0; s < 9; s++) {
            int ks = rb + s;
            wmma::fragment<wmma::matrix_a, 16, 16, 16, __half, wmma::row_major> ap;
            wmma::load_matrix_sync(ap, Ph + (size_t)(rb * 16) * AP_LD + ks * 16, AP_LD);
            #pragma unroll
            for (int j = 0; j < 2; j++) {
                wmma::fragment<wmma::matrix_b, 16, 16, 16, __half, wmma::row_major> bv;
                wmma::load_matrix_sync(bv, Vh + (size_t)(ks * 16) * AQ_LD + (cb0 + j) * 16, AQ_LD);
                wmma::mma_sync(oacc[j], ap, bv, oacc[j]);
            }
        }
        float* Of = Sf;
        #pragma unroll
        for (int j = 0; j < 2; j++)
            wmma::store_matrix_sync(Of + (size_t)(rb * 16) * AO_LD + (cb0 + j) * 16,
                                    oacc[j], AO_LD, wmma::mem_row_major);
    }
    __syncthreads();

    // ---- scale by Inv[q], emit half ----
    {
        float* Of = Sf;
        for (int idx = tid; idx < 64 * 16; idx += 256) {
            int q = idx >> 4, d4 = idx & 15;
            float inv = Inv[q];
            float4 v = *(float4*)(Of + (size_t)q * AO_LD + d4 * 4);
            __half2 h0 = __floats2half2_rn(v.x * inv, v.y * inv);
            __half2 h1 = __floats2half2_rn(v.z * inv, v.w * inv);
            __half2* p = (__half2*)(out + ((size_t)(b * TT + q0 + q)) * DIM + h * HD + d4 * 4);
            p[0] = h0; p[1] = h1;
        }
    }
}

// ================= launcher =================
extern "C" void kernel_launch(void* const* d_in, const int* in_sizes, int n_in,
                              void* d_out, int out_size)
{
    const float* x       = (const float*)d_in[0];
    const float* norm1_w = (const float*)d_in[1];
    const float* norm2_w = (const float*)d_in[2];
    const float* w_qkv   = (const float*)d_in[3];
    const float* w_out   = (const float*)d_in[4];
    const float* b_out   = (const float*)d_in[5];
    const float* w1      = (const float*)d_in[6];
    const float* b1      = (const float*)d_in[7];
    const float* w2      = (const float*)d_in[8];
    const float* b2      = (const float*)d_in[9];
    float* y = (float*)d_out;

    __half *xn, *qkv, *attn, *hbuf, *wh;
    float *x1;
    cudaGetSymbolAddress((void**)&xn,   g_xn_h);
    cudaGetSymbolAddress((void**)&qkv,  g_qkv_h);
    cudaGetSymbolAddress((void**)&attn, g_attn_h);
    cudaGetSymbolAddress((void**)&hbuf, g_hbuf_h);
    cudaGetSymbolAddress((void**)&x1,   g_x1);
    cudaGetSymbolAddress((void**)&wh,   g_w_h);

    static_assert(ATTN_SMEM <= 113 * 1024, "attn smem must allow 2 CTAs/SM");
    static_assert(GEMM_SMEM <= 113 * 1024, "gemm smem must allow 2 CTAs/SM");
    cudaFuncSetAttribute(attn_kernel, cudaFuncAttributeMaxDynamicSharedMemorySize, ATTN_SMEM);
    cudaFuncSetAttribute(gemm_h_kernel<0>, cudaFuncAttributeMaxDynamicSharedMemorySize, GEMM_SMEM);
    cudaFuncSetAttribute(gemm_h_kernel<1>, cudaFuncAttributeMaxDynamicSharedMemorySize, GEMM_SMEM);
    cudaFuncSetAttribute(gemm_h_kernel<2>, cudaFuncAttributeMaxDynamicSharedMemorySize, GEMM_SMEM);

    // 0. convert all weights to fp16 (one launch)
    f2h_all_kernel<<<(F4_TOT + 255) / 256, 256>>>(w_qkv, w_out, w1, w2, wh);

    // 1. rmsnorm(x) -> xn (half)
    rmsnorm_kernel<<<ROWS, 256>>>(x, norm1_w, xn);
    // 2. qkv = xn @ w_qkv (half out)
    gemm_h_kernel<0><<<dim3((3 * DIM) / 128, ROWS / 128), 256, GEMM_SMEM>>>(
        xn, wh + WQKV_OFF, nullptr, nullptr, qkv, 3 * DIM, DIM);
    // 3. banded attention (tensor-core) -> attn (half)
    attn_kernel<<<dim3(TT / 64, NHEAD, BB), 256, ATTN_SMEM>>>(qkv, attn);
    // 4. x1 = x + attn @ w_out + b_out (float out)
    gemm_h_kernel<2><<<dim3(DIM / 128, ROWS / 128), 256, GEMM_SMEM>>>(
        attn, wh + WOUT_OFF, b_out, x, x1, DIM, DIM);
    // 5. rmsnorm(x1) -> xn (half)
    rmsnorm_kernel<<<ROWS, 256>>>(x1, norm2_w, xn);
    // 6. h = gelu(xn @ w1 + b1) (half out)
    gemm_h_kernel<1><<<dim3(FFN / 128, ROWS / 128), 256, GEMM_SMEM>>>(
        xn, wh + W1_OFF, b1, nullptr, hbuf, FFN, DIM);
    // 7. y = x1 + h @ w2 + b2 (float out)
    gemm_h_kernel<2><<<dim3(DIM / 128, ROWS / 128), 256, GEMM_SMEM>>>(
        hbuf, wh + W2_OFF, b2, x1, y, DIM, FFN);
}

// round 17
// speedup vs baseline: 1.0477x; 1.0477x over previous
#include <cuda_runtime.h>
#include <cuda_fp16.h>
#include <mma.h>
#include <math.h>
#include <stdint.h>

using namespace nvcuda;

#define DIM   512
#define NHEAD 8
#define HD    64
#define FFN   2048
#define BB    4
#define TT    2048
#define ROWS  (BB*TT)     // 8192
#define CTX   64

// ---------------- scratch (allocation-free) ----------------
__device__ __half g_xn_h  [ROWS * DIM];
__device__ __half g_qkv_h [ROWS * 3 * DIM];
__device__ __half g_attn_h[ROWS * DIM];
__device__ __half g_hbuf_h[ROWS * FFN];
__device__ float  g_x1    [ROWS * DIM];
// fp16 weights
#define WQKV_OFF 0
#define WOUT_OFF (3 * DIM * DIM)
#define W1_OFF   (WOUT_OFF + DIM * DIM)
#define W2_OFF   (W1_OFF + DIM * FFN)
#define WTOT     (W2_OFF + FFN * DIM)
__device__ __half g_w_h[WTOT];

// ================= helpers =================
__device__ __forceinline__ uint32_t smem_u32(const void* p) {
    uint32_t a;
    asm("{ .reg .u64 t; cvta.to.shared.u64 t, %1; cvt.u32.u64 %0, t; }" : "=r"(a) : "l"(p));
    return a;
}
__device__ __forceinline__ void cp_async16(uint32_t saddr, const void* gaddr) {
    asm volatile("cp.async.cg.shared.global [%0], [%1], 16;" :: "r"(saddr), "l"(gaddr));
}
#define CP_COMMIT() asm volatile("cp.async.commit_group;" ::: "memory")
#define CP_WAIT(n)  asm volatile("cp.async.wait_group %0;" :: "n"(n) : "memory")

// ---- weight-convert task sizes (float4 units) ----
#define F4_QKV (3 * DIM * DIM / 4)
#define F4_OUT (DIM * DIM / 4)
#define F4_W1  (DIM * FFN / 4)
#define F4_W2  (FFN * DIM / 4)
#define F4_TOT (F4_QKV + F4_OUT + F4_W1 + F4_W2)   // 786432
#define WCONV_BLOCKS ((F4_TOT + 255) / 256)        // 3072

// ================= fused front kernel: rmsnorm(x) + weight f2h =================
// blocks [0, ROWS): rmsnorm row; blocks [ROWS, ROWS+WCONV_BLOCKS): weight convert
__global__ void __launch_bounds__(256) front_kernel(
    const float* __restrict__ x, const float* __restrict__ w, __half* __restrict__ y,
    const float* __restrict__ w_qkv, const float* __restrict__ w_out,
    const float* __restrict__ w1, const float* __restrict__ w2,
    __half* __restrict__ wh)
{
    int blk = blockIdx.x;
    int t = threadIdx.x;
    if (blk < ROWS) {
        // ---- rmsnorm ----
        const float* xr = x + (size_t)blk * DIM;
        float v0 = xr[t], v1 = xr[t + 256];
        float s = v0 * v0 + v1 * v1;
        #pragma unroll
        for (int o = 16; o; o >>= 1) s += __shfl_xor_sync(0xffffffffu, s, o);
        __shared__ float red[8];
        if ((t & 31) == 0) red[t >> 5] = s;
        __syncthreads();
        if (t < 8) {
            float r = red[t];
            #pragma unroll
            for (int o = 4; o; o >>= 1) r += __shfl_xor_sync(0xffu, r, o);
            if (t == 0) red[0] = r;
        }
        __syncthreads();
        float inv = 1.0f / sqrtf(red[0] * (1.0f / DIM) + 1e-6f);
        __half* yr = y + (size_t)blk * DIM;
        yr[t]       = __float2half_rn(v0 * inv * w[t]);
        yr[t + 256] = __float2half_rn(v1 * inv * w[t + 256]);
    } else {
        // ---- weight convert ----
        int i = (blk - ROWS) * 256 + t;
        if (i >= F4_TOT) return;
        const float* src;
        int rel;
        size_t dsth;
        if (i < F4_QKV) {
            src = w_qkv; rel = i; dsth = WQKV_OFF;
        } else if (i < F4_QKV + F4_OUT) {
            src = w_out; rel = i - F4_QKV; dsth = WOUT_OFF;
        } else if (i < F4_QKV + F4_OUT + F4_W1) {
            src = w1; rel = i - F4_QKV - F4_OUT; dsth = W1_OFF;
        } else {
            src = w2; rel = i - F4_QKV - F4_OUT - F4_W1; dsth = W2_OFF;
        }
        float4 v = ((const float4*)src)[rel];
        __half2 h0 = __floats2half2_rn(v.x, v.y);
        __half2 h1 = __floats2half2_rn(v.z, v.w);
        __half2* p = (__half2*)(wh + dsth) + rel * 2;
        p[0] = h0; p[1] = h1;
    }
}

// ================= RMSNorm (half output) =================
__global__ void __launch_bounds__(256) rmsnorm_kernel(
    const float* __restrict__ x, const float* __restrict__ w, __half* __restrict__ y)
{
    int row = blockIdx.x;
    int t = threadIdx.x;
    const float* xr = x + (size_t)row * DIM;
    float v0 = xr[t], v1 = xr[t + 256];
    float s = v0 * v0 + v1 * v1;
    #pragma unroll
    for (int o = 16; o; o >>= 1) s += __shfl_xor_sync(0xffffffffu, s, o);
    __shared__ float red[8];
    if ((t & 31) == 0) red[t >> 5] = s;
    __syncthreads();
    if (t < 8) {
        float r = red[t];
        #pragma unroll
        for (int o = 4; o; o >>= 1) r += __shfl_xor_sync(0xffu, r, o);
        if (t == 0) red[0] = r;
    }
    __syncthreads();
    float inv = 1.0f / sqrtf(red[0] * (1.0f / DIM) + 1e-6f);
    __half* yr = y + (size_t)row * DIM;
    yr[t]       = __float2half_rn(v0 * inv * w[t]);
    yr[t + 256] = __float2half_rn(v1 * inv * w[t + 256]);
}

// ================= wmma fp16 GEMM: 128x128 CTA, 2-stage, occ 2 (r15 verbatim) =================
#define KC     64
#define LDA    72
#define LDB    144
#define A_STG_H (128 * LDA)
#define B_STG_H (KC * LDB)
#define STG_H   (A_STG_H + B_STG_H)
#define LDST    136
#define GEMM_SMEM (2 * STG_H * 2)    // 73728 B

template<int EPI>
__global__ void __launch_bounds__(128, 2) gemm_h_kernel(
    const __half* __restrict__ A, const __half* __restrict__ Bg,
    const float* __restrict__ bias, const float* __restrict__ res,
    void* __restrict__ Cv, int N, int K)
{
    extern __shared__ char smraw[];
    __half* smh = (__half*)smraw;
    uint32_t sm_base = smem_u32(smraw);

    int tid = threadIdx.x;
    int wid = tid >> 5;
    int m0 = blockIdx.y * 128;
    int n0 = blockIdx.x * 128;
    int wm = wid >> 1;
    int wn = wid & 1;

    const int nc = K / KC;

    auto issue_chunk = [&](int ic) {
        uint32_t as_addr = sm_base + (uint32_t)((ic & 1) * STG_H) * 2;
        uint32_t bs_addr = as_addr + A_STG_H * 2;
        #pragma unroll
        for (int i = 0; i < 8; i++) {
            int task = tid + i * 128;
            int r = task >> 3, sg = task & 7;
            cp_async16(as_addr + (uint32_t)(r * LDA + sg * 8) * 2,
                       A + (size_t)(m0 + r) * K + ic * KC + sg * 8);
        }
        #pragma unroll
        for (int i = 0; i < 8; i++) {
            int task = tid + i * 128;
            int r = task >> 4, sg = task & 15;
            cp_async16(bs_addr + (uint32_t)(r * LDB + sg * 8) * 2,
                       Bg + (size_t)(ic * KC + r) * N + n0 + sg * 8);
        }
    };

    wmma::fragment<wmma::accumulator, 16, 16, 16, float> acc[4][4];
    #pragma unroll
    for (int i = 0; i < 4; i++)
        #pragma unroll
        for (int j = 0; j < 4; j++)
            wmma::fill_fragment(acc[i][j], 0.0f);

    issue_chunk(0); CP_COMMIT();

    for (int ic = 0; ic < nc; ic++) {
        if (ic + 1 < nc) { issue_chunk(ic + 1); CP_COMMIT(); CP_WAIT(1); }
        else             { CP_WAIT(0); }
        __syncthreads();

        __half* As = smh + (ic & 1) * STG_H;
        __half* Bs = As + A_STG_H;
        #pragma unroll
        for (int ks = 0; ks < 4; ks++) {
            wmma::fragment<wmma::matrix_a, 16, 16, 16, __half, wmma::row_major> af[4];
            wmma::fragment<wmma::matrix_b, 16, 16, 16, __half, wmma::row_major> bf[4];
            #pragma unroll
            for (int i = 0; i < 4; i++)
                wmma::load_matrix_sync(af[i], As + (size_t)(wm * 64 + i * 16) * LDA + ks * 16, LDA);
            #pragma unroll
            for (int j = 0; j < 4; j++)
                wmma::load_matrix_sync(bf[j], Bs + (size_t)(ks * 16) * LDB + wn * 64 + j * 16, LDB);
            #pragma unroll
            for (int i = 0; i < 4; i++)
                #pragma unroll
                for (int j = 0; j < 4; j++)
                    wmma::mma_sync(acc[i][j], af[i], bf[j], acc[i][j]);
        }
        __syncthreads();
    }

    float* stage = (float*)smraw;
    #pragma unroll
    for (int i = 0; i < 4; i++)
        #pragma unroll
        for (int j = 0; j < 4; j++)
            wmma::store_matrix_sync(stage + (size_t)(wm * 64 + i * 16) * LDST + wn * 64 + j * 16,
                                    acc[i][j], LDST, wmma::mem_row_major);
    __syncthreads();

    #pragma unroll
    for (int jj = 0; jj < 32; jj++) {
        int idx = jj * 128 + tid;
        int m = idx >> 5, g = idx & 31;
        float4 v = *(float4*)(stage + (size_t)m * LDST + g * 4);
        int c = n0 + g * 4;
        if (EPI == 2) {
            float4 b = *(const float4*)(bias + c);
            float4 rr = *(const float4*)(res + (size_t)(m0 + m) * N + c);
            v.x += b.x + rr.x; v.y += b.y + rr.y;
            v.z += b.z + rr.z; v.w += b.w + rr.w;
            *(float4*)((float*)Cv + (size_t)(m0 + m) * N + c) = v;
        } else {
            if (EPI == 1) {
                float4 b = *(const float4*)(bias + c);
                v.x += b.x; v.y += b.y; v.z += b.z; v.w += b.w;
                v.x = 0.5f * v.x * (1.0f + erff(v.x * 0.70710678118654752f));
                v.y = 0.5f * v.y * (1.0f + erff(v.y * 0.70710678118654752f));
                v.z = 0.5f * v.z * (1.0f + erff(v.z * 0.70710678118654752f));
                v.w = 0.5f * v.w * (1.0f + erff(v.w * 0.70710678118654752f));
            }
            __half2 h0 = __floats2half2_rn(v.x, v.y);
            __half2 h1 = __floats2half2_rn(v.z, v.w);
            __half2* p = (__half2*)((__half*)Cv + (size_t)(m0 + m) * N + c);
            p[0] = h0; p[1] = h1;
        }
    }
}

// ================= Banded attention (r12/r15 verbatim): tensor-core, occ 2, block-skipping =================
#define AQ_LD 72    // halves
#define AS_LD 196   // floats
#define AP_LD 200   // halves
#define AO_LD 72    // floats
#define AT_Q   0
#define AT_K   (AT_Q + 64 * AQ_LD * 2)
#define AT_V   0                                      // overlays Q+K after softmax
#define AT_S   (AT_K + 192 * AQ_LD * 2)
#define AT_P   (AT_S + 64 * AS_LD * 4)
#define AT_I   (AT_P + 64 * AP_LD * 2)
#define ATTN_SMEM (AT_I + 64 * 4)                    // 112896 B

__global__ void __launch_bounds__(256, 2) attn_kernel(
    const __half* __restrict__ qkv, __half* __restrict__ out)
{
    extern __shared__ char smraw[];
    __half* Qh = (__half*)(smraw + AT_Q);
    __half* Kh = (__half*)(smraw + AT_K);
    __half* Vh = (__half*)(smraw + AT_V);
    float*  Sf = (float*) (smraw + AT_S);
    __half* Ph = (__half*)(smraw + AT_P);
    float*  Inv = (float*)(smraw + AT_I);

    int tid = threadIdx.x;
    int wid = tid >> 5;
    int qt = blockIdx.x, h = blockIdx.y, b = blockIdx.z;
    int q0 = qt * 64;
    int kbase = q0 - CTX;

    // ---- load Q and K; zero-prefill P ----
    for (int idx = tid; idx < 64 * 8; idx += 256) {
        int r = idx >> 3, d8 = idx & 7;
        uint4 v = *(const uint4*)(qkv + ((size_t)(b * TT + q0 + r)) * (3 * DIM) + h * HD + d8 * 8);
        *(uint4*)(Qh + r * AQ_LD + d8 * 8) = v;
    }
    for (int idx = tid; idx < 192 * 8; idx += 256) {
        int r = idx >> 3, d8 = idx & 7;
        int kg = kbase + r;
        uint4 kvv = {0, 0, 0, 0};
        if (kg >= 0 && kg < TT)
            kvv = *(const uint4*)(qkv + ((size_t)(b * TT + kg)) * (3 * DIM) + h * HD + DIM + d8 * 8);
        *(uint4*)(Kh + r * AQ_LD + d8 * 8) = kvv;
    }
    {   // zero P: 64 rows x 200 halves = 1600 uint4
        uint4 z = {0, 0, 0, 0};
        for (int idx = tid; idx < 1600; idx += 256) {
            int r = idx / 25, d8 = idx % 25;
            *(uint4*)(Ph + r * AP_LD + d8 * 8) = z;
        }
    }
    __syncthreads();

    // ---- S = Q @ K^T (banded: only col-blocks [rb, rb+8] can be valid) ----
    {
        int rb = wid & 3;
        int cb0 = (wid >> 2) * 6;
        wmma::fragment<wmma::accumulator, 16, 16, 16, float> sacc[6];
        #pragma unroll
        for (int j = 0; j < 6; j++) wmma::fill_fragment(sacc[j], 0.0f);
        #pragma unroll
        for (int ks = 0; ks < 4; ks++) {
            wmma::fragment<wmma::matrix_a, 16, 16, 16, __half, wmma::row_major> aq;
            wmma::load_matrix_sync(aq, Qh + (size_t)(rb * 16) * AQ_LD + ks * 16, AQ_LD);
            #pragma unroll
            for (int j = 0; j < 6; j++) {
                int cb = cb0 + j;
                if (cb >= rb && cb <= rb + 8) {
                    wmma::fragment<wmma::matrix_b, 16, 16, 16, __half, wmma::col_major> bk;
                    wmma::load_matrix_sync(bk, Kh + (size_t)(cb * 16) * AQ_LD + ks * 16, AQ_LD);
                    wmma::mma_sync(sacc[j], aq, bk, sacc[j]);
                }
            }
        }
        #pragma unroll
        for (int j = 0; j < 6; j++) {
            int cb = cb0 + j;
            if (cb >= rb && cb <= rb + 8)
                wmma::store_matrix_sync(Sf + (size_t)(rb * 16) * AS_LD + cb * 16,
                                        sacc[j], AS_LD, wmma::mem_row_major);
        }
    }
    __syncthreads();

    // ---- softmax over valid range [lo, hi]; P elsewhere already 0 ----
    {
        const float scale = 0.125f;
        int q = tid >> 2, l = tid & 3;
        int lo = q, t0 = -kbase;
        if (t0 > lo) lo = t0;
        int hi = q + 2 * CTX;
        int t1 = TT - 1 - kbase;
        if (t1 < hi) hi = t1;
        float mx = -1e30f;
        for (int kk = lo + l; kk <= hi; kk += 4)
            mx = fmaxf(mx, Sf[q * AS_LD + kk]);
        mx = fmaxf(mx, __shfl_xor_sync(0xffffffffu, mx, 1));
        mx = fmaxf(mx, __shfl_xor_sync(0xffffffffu, mx, 2));
        mx *= scale;
        float sum = 0.f;
        for (int kk = lo + l; kk <= hi; kk += 4) {
            float e = __expf(Sf[q * AS_LD + kk] * scale - mx);
            Ph[q * AP_LD + kk] = __float2half_rn(e);
            sum += e;
        }
        sum += __shfl_xor_sync(0xffffffffu, sum, 1);
        sum += __shfl_xor_sync(0xffffffffu, sum, 2);
        if (l == 0) Inv[q] = 1.0f / sum;
    }
    __syncthreads();

    // ---- load V into dead Q+K region ----
    for (int idx = tid; idx < 192 * 8; idx += 256) {
        int r = idx >> 3, d8 = idx & 7;
        int kg = kbase + r;
        uint4 vvv = {0, 0, 0, 0};
        if (kg >= 0 && kg < TT)
            vvv = *(const uint4*)(qkv + ((size_t)(b * TT + kg)) * (3 * DIM) + h * HD + 2 * DIM + d8 * 8);
        *(uint4*)(Vh + r * AQ_LD + d8 * 8) = vvv;
    }
    __syncthreads();

    // ---- O = P @ V (banded: k-steps rb..rb+8 only; P zero outside) ----
    {
        int rb = wid & 3;
        int cb0 = (wid >> 2) * 2;
        wmma::fragment<wmma::accumulator, 16, 16, 16, float> oacc[2];
        #pragma unroll
        for (int j = 0; j < 2; j++) wmma::fill_fragment(oacc[j], 0.0f);
        #pragma unroll
        for (int s = 0; s < 9; s++) {
            int ks = rb + s;
            wmma::fragment<wmma::matrix_a, 16, 16, 16, __half, wmma::row_major> ap;
            wmma::load_matrix_sync(ap, Ph + (size_t)(rb * 16) * AP_LD + ks * 16, AP_LD);
            #pragma unroll
            for (int j = 0; j < 2; j++) {
                wmma::fragment<wmma::matrix_b, 16, 16, 16, __half, wmma::row_major> bv;
                wmma::load_matrix_sync(bv, Vh + (size_t)(ks * 16) * AQ_LD + (cb0 + j) * 16, AQ_LD);
                wmma::mma_sync(oacc[j], ap, bv, oacc[j]);
            }
        }
        float* Of = Sf;
        #pragma unroll
        for (int j = 0; j < 2; j++)
            wmma::store_matrix_sync(Of + (size_t)(rb * 16) * AO_LD + (cb0 + j) * 16,
                                    oacc[j], AO_LD, wmma::mem_row_major);
    }
    __syncthreads();

    // ---- scale by Inv[q], emit half ----
    {
        float* Of = Sf;
        for (int idx = tid; idx < 64 * 16; idx += 256) {
            int q = idx >> 4, d4 = idx & 15;
            float inv = Inv[q];
            float4 v = *(float4*)(Of + (size_t)q * AO_LD + d4 * 4);
            __half2 h0 = __floats2half2_rn(v.x * inv, v.y * inv);
            __half2 h1 = __floats2half2_rn(v.z * inv, v.w * inv);
            __half2* p = (__half2*)(out + ((size_t)(b * TT + q0 + q)) * DIM + h * HD + d4 * 4);
            p[0] = h0; p[1] = h1;
        }
    }
}

// ================= launcher =================
extern "C" void kernel_launch(void* const* d_in, const int* in_sizes, int n_in,
                              void* d_out, int out_size)
{
    const float* x       = (const float*)d_in[0];
    const float* norm1_w = (const float*)d_in[1];
    const float* norm2_w = (const float*)d_in[2];
    const float* w_qkv   = (const float*)d_in[3];
    const float* w_out   = (const float*)d_in[4];
    const float* b_out   = (const float*)d_in[5];
    const float* w1      = (const float*)d_in[6];
    const float* b1      = (const float*)d_in[7];
    const float* w2      = (const float*)d_in[8];
    const float* b2      = (const float*)d_in[9];
    float* y = (float*)d_out;

    __half *xn, *qkv, *attn, *hbuf, *wh;
    float *x1;
    cudaGetSymbolAddress((void**)&xn,   g_xn_h);
    cudaGetSymbolAddress((void**)&qkv,  g_qkv_h);
    cudaGetSymbolAddress((void**)&attn, g_attn_h);
    cudaGetSymbolAddress((void**)&hbuf, g_hbuf_h);
    cudaGetSymbolAddress((void**)&x1,   g_x1);
    cudaGetSymbolAddress((void**)&wh,   g_w_h);

    static_assert(ATTN_SMEM <= 113 * 1024, "attn smem must allow 2 CTAs/SM");
    static_assert(GEMM_SMEM <= 113 * 1024, "gemm smem must allow 2 CTAs/SM");
    cudaFuncSetAttribute(attn_kernel, cudaFuncAttributeMaxDynamicSharedMemorySize, ATTN_SMEM);
    cudaFuncSetAttribute(gemm_h_kernel<0>, cudaFuncAttributeMaxDynamicSharedMemorySize, GEMM_SMEM);
    cudaFuncSetAttribute(gemm_h_kernel<1>, cudaFuncAttributeMaxDynamicSharedMemorySize, GEMM_SMEM);
    cudaFuncSetAttribute(gemm_h_kernel<2>, cudaFuncAttributeMaxDynamicSharedMemorySize, GEMM_SMEM);

    // 1. fused: rmsnorm(x) -> xn  AND  all weights -> fp16 (one launch)
    front_kernel<<<ROWS + WCONV_BLOCKS, 256>>>(x, norm1_w, xn,
                                               w_qkv, w_out, w1, w2, wh);
    // 2. qkv = xn @ w_qkv (half out)
    gemm_h_kernel<0><<<dim3((3 * DIM) / 128, ROWS / 128), 128, GEMM_SMEM>>>(
        xn, wh + WQKV_OFF, nullptr, nullptr, qkv, 3 * DIM, DIM);
    // 3. banded attention (tensor-core) -> attn (half)
    attn_kernel<<<dim3(TT / 64, NHEAD, BB), 256, ATTN_SMEM>>>(qkv, attn);
    // 4. x1 = x + attn @ w_out + b_out (float out)
    gemm_h_kernel<2><<<dim3(DIM / 128, ROWS / 128), 128, GEMM_SMEM>>>(
        attn, wh + WOUT_OFF, b_out, x, x1, DIM, DIM);
    // 5. rmsnorm(x1) -> xn (half)
    rmsnorm_kernel<<<ROWS, 256>>>(x1, norm2_w, xn);
    // 6. h = gelu(xn @ w1 + b1) (half out)
    gemm_h_kernel<1><<<dim3(FFN / 128, ROWS / 128), 128, GEMM_SMEM>>>(
        xn, wh + W1_OFF, b1, nullptr, hbuf, FFN, DIM);
    // 7. y = x1 + h @ w2 + b2 (float out)
    gemm_h_kernel<2><<<dim3(DIM / 128, ROWS / 128), 128, GEMM_SMEM>>>(
        hbuf, wh + W2_OFF, b2, x1, y, DIM, FFN);
}